// round 16
// baseline (speedup 1.0000x reference)
#include <cuda_runtime.h>
#include <math.h>

#define Cc   64
#define Hh   96
#define Ww   96
#define COo  64
#define KKt  9
#define HW   (Hh*Ww)

typedef unsigned long long ull;

__device__ __forceinline__ ull ffma2(ull a, ull b, ull c) {
    ull d;
    asm("fma.rn.f32x2 %0, %1, %2, %3;" : "=l"(d) : "l"(a), "l"(b), "l"(c));
    return d;
}
__device__ __forceinline__ ull pack2(float x, float y) {
    ull d; asm("mov.b64 %0, {%1, %2};" : "=l"(d) : "f"(x), "f"(y)); return d;
}
__device__ __forceinline__ float2 unpack2(ull v) {
    float2 r; asm("mov.b64 {%0, %1}, %2;" : "=f"(r.x), "=f"(r.y) : "l"(v)); return r;
}

// Transposed weights (device scratch; no allocs allowed)
__device__ float g_wT[KKt*Cc*COo];    // [kk][c][co]
__device__ float g_woffT[KKt*Cc*32];  // [kk][c][slot=co], co<27 valid, else 0

__global__ void prep_weights(const float* __restrict__ w,
                             const float* __restrict__ w_off) {
    int i = blockIdx.x*blockDim.x + threadIdx.x;
    int stride = gridDim.x*blockDim.x;
    for (int idx = i; idx < KKt*Cc*COo; idx += stride) {
        int kk = idx / (Cc*COo);
        int r  = idx % (Cc*COo);
        int c  = r >> 6, co = r & 63;
        g_wT[idx] = w[(co*Cc + c)*KKt + kk];
    }
    for (int idx = i; idx < KKt*Cc*32; idx += stride) {
        int kk = idx / (Cc*32);
        int r  = idx % (Cc*32);
        int c  = r >> 5, slot = r & 31;
        float v = 0.f;
        if (slot < 27) v = w_off[(slot*Cc + c)*KKt + kk];
        g_woffT[idx] = v;
    }
}

// Fused: offset conv -> bilinear precompute -> deform conv GEMM, f32x2 math.
// Block: 128 threads = 16 px-quads (64 px, 32x2 tile) x 8 groups. Grid: (144, 8).
// Thread tile: 4 consecutive pixels x 8 output channels.
__global__ __launch_bounds__(128) void fused_dcn(
    const float* __restrict__ x, const float* __restrict__ b_off,
    const float* __restrict__ bias, float* __restrict__ out)
{
    __shared__ __align__(16) float s_patch[64*64]; // [c][p]; aliased as s_off[p][28]
    __shared__ __align__(16) float s_w[64*64];     // weight chunk [c][co] / [c][32]
    __shared__ __align__(16) float s_bil[64*9*6];  // per (p,kk): w00..w11, baseIdx, steps

    const int tid  = threadIdx.x;
    const int quad = tid & 15;      // pixel-quad index: pixels 4q..4q+3 (same row)
    const int g    = tid >> 4;      // group 0..7 (c-chunk 8 for gather, co-chunk for GEMM)
    const int n    = blockIdx.y;
    const int txi  = blockIdx.x % 3;
    const int tyi  = blockIdx.x / 3;
    const int p0   = 4*quad;
    const int pw0  = txi*32 + (p0 & 31);  // multiple of 4; quad spans pw0..pw0+3
    const int ph   = tyi*2  + (p0 >> 5);

    const float* __restrict__ xn = x + n*Cc*HW;

    // ---------------- Phase 1: offset conv (27 out ch, padded to 32) ----------------
    // thread: 4 px x 4 co (co = 4g..4g+3) as 2 co-pairs per px
    ull acc1[4][2];
    #pragma unroll
    for (int i = 0; i < 4; i++) { acc1[i][0] = 0ull; acc1[i][1] = 0ull; }

    for (int kk = 0; kk < 9; kk++) {
        const int ky = kk/3 - 1, kx = kk%3 - 1;
        __syncthreads();
        // integer-tap patch gather: c-chunk 8, 4 px each (zero pad)
        {
            int yy  = ph + ky;
            int xxb = pw0 + kx;
            bool oky = (yy >= 0) & (yy < Hh);
            bool ok0 = oky & (xxb   >= 0) & (xxb   < Ww);
            bool ok1 = oky & (xxb+1 >= 0) & (xxb+1 < Ww);
            bool ok2 = oky & (xxb+2 >= 0) & (xxb+2 < Ww);
            bool ok3 = oky & (xxb+3 >= 0) & (xxb+3 < Ww);
            int base = yy*Ww + xxb;
            #pragma unroll
            for (int i = 0; i < 8; i++) {
                int c = g*8 + i;
                const float* xc = xn + c*HW + base;
                float4 v;
                v.x = ok0 ? __ldg(xc + 0) : 0.f;
                v.y = ok1 ? __ldg(xc + 1) : 0.f;
                v.z = ok2 ? __ldg(xc + 2) : 0.f;
                v.w = ok3 ? __ldg(xc + 3) : 0.f;
                *(float4*)(s_patch + c*64 + p0) = v;
            }
        }
        // offset-weight chunk [c][32] : 2048 floats, 4 float4 per thread
        {
            const float4* src = (const float4*)(g_woffT + kk*Cc*32);
            float4* dst = (float4*)s_w;
            #pragma unroll
            for (int i = 0; i < 4; i++) dst[tid + i*128] = src[tid + i*128];
        }
        __syncthreads();
        #pragma unroll 4
        for (int c = 0; c < 64; c++) {
            float4 xq = *(const float4*)(s_patch + c*64 + p0);
            ulonglong2 wp = *(const ulonglong2*)(s_w + c*32 + g*4);
            ull x0 = pack2(xq.x, xq.x);
            ull x1 = pack2(xq.y, xq.y);
            ull x2 = pack2(xq.z, xq.z);
            ull x3 = pack2(xq.w, xq.w);
            acc1[0][0] = ffma2(x0, wp.x, acc1[0][0]);
            acc1[0][1] = ffma2(x0, wp.y, acc1[0][1]);
            acc1[1][0] = ffma2(x1, wp.x, acc1[1][0]);
            acc1[1][1] = ffma2(x1, wp.y, acc1[1][1]);
            acc1[2][0] = ffma2(x2, wp.x, acc1[2][0]);
            acc1[2][1] = ffma2(x2, wp.y, acc1[2][1]);
            acc1[3][0] = ffma2(x3, wp.x, acc1[3][0]);
            acc1[3][1] = ffma2(x3, wp.y, acc1[3][1]);
        }
    }

    __syncthreads();
    // stash conv result as s_off[p][28] (aliases s_patch)
    {
        float* s_off = s_patch;
        #pragma unroll
        for (int j = 0; j < 2; j++) {
            int co0 = g*4 + 2*j, co1 = co0 + 1;
            float b0 = (co0 < 27) ? __ldg(b_off + co0) : 0.f;
            float b1 = (co1 < 27) ? __ldg(b_off + co1) : 0.f;
            #pragma unroll
            for (int px = 0; px < 4; px++) {
                float2 v = unpack2(acc1[px][j]);
                if (co0 < 27) s_off[(p0+px)*28 + co0] = v.x + b0;
                if (co1 < 27) s_off[(p0+px)*28 + co1] = v.y + b1;
            }
        }
    }
    __syncthreads();

    // ---------------- Phase 2: bilinear/mask precompute ----------------
    {
        const float* s_off = s_patch;
        for (int i = tid; i < 576; i += 128) {
            int pp = i / 9, kk = i % 9;
            int ky = kk / 3, kx = kk % 3;
            int iph = tyi*2  + (pp >> 5);
            int ipw = txi*32 + (pp & 31);
            float dy = s_off[pp*28 + 2*kk];
            float dx = s_off[pp*28 + 2*kk + 1];
            float m  = s_off[pp*28 + 18 + kk];
            float sig = 1.f / (1.f + __expf(-m));
            float py = dy + (float)(ky + iph - 1);
            float px = dx + (float)(kx + ipw - 1);
            float y0f = floorf(py), x0f = floorf(px);
            float ly = py - y0f, lx = px - x0f;
            int y0 = (int)y0f, x0 = (int)x0f;
            int y1 = y0 + 1,   x1 = x0 + 1;
            float vy0 = (y0 >= 0 && y0 < Hh) ? 1.f : 0.f;
            float vy1 = (y1 >= 0 && y1 < Hh) ? 1.f : 0.f;
            float vx0 = (x0 >= 0 && x0 < Ww) ? 1.f : 0.f;
            float vx1 = (x1 >= 0 && x1 < Ww) ? 1.f : 0.f;
            float w00 = (1.f-ly)*(1.f-lx)*sig*vy0*vx0;
            float w01 = (1.f-ly)*lx      *sig*vy0*vx1;
            float w10 = ly      *(1.f-lx)*sig*vy1*vx0;
            float w11 = ly      *lx      *sig*vy1*vx1;
            int y0c = min(max(y0, 0), Hh-1);
            int x0c = min(max(x0, 0), Ww-1);
            int y1c = min(max(y1, 0), Hh-1);
            int x1c = min(max(x1, 0), Ww-1);
            int sy = (y1c - y0c) * Ww;   // 0 or 96
            int sx = (x1c - x0c);        // 0 or 1
            float* d = s_bil + i*6;
            d[0] = w00; d[1] = w01; d[2] = w10; d[3] = w11;
            ((int*)d)[4] = y0c*Ww + x0c;
            ((int*)d)[5] = sy | (sx << 12);
        }
    }

    // ---------------- Phase 3: deformable gather + main GEMM ----------------
    // thread: 4 px x 8 co (co = 8g..8g+7) as 4 co-pairs per px
    ull acc[4][4];
    #pragma unroll
    for (int i = 0; i < 4; i++)
        #pragma unroll
        for (int j = 0; j < 4; j++) acc[i][j] = 0ull;

    for (int kk = 0; kk < 9; kk++) {
        __syncthreads();
        // main weight chunk [c][co]: 4096 floats, 8 float4 per thread
        {
            const float4* src = (const float4*)(g_wT + kk*Cc*COo);
            float4* dst = (float4*)s_w;
            #pragma unroll
            for (int i = 0; i < 8; i++) dst[tid + i*128] = src[tid + i*128];
        }
        // bilinear gather: c-chunk 8, 4 px each
        {
            float c00[4], c01[4], c10[4], c11[4];
            int i00[4], i01[4], i10[4], i11[4];
            #pragma unroll
            for (int px = 0; px < 4; px++) {
                const float* d = s_bil + ((p0+px)*9 + kk)*6;
                c00[px] = d[0]; c01[px] = d[1]; c10[px] = d[2]; c11[px] = d[3];
                int base = ((const int*)d)[4];
                int st   = ((const int*)d)[5];
                int sy = st & 0xFFF, sx = st >> 12;
                i00[px] = base; i01[px] = base + sx;
                i10[px] = base + sy; i11[px] = base + sy + sx;
            }
            #pragma unroll
            for (int i = 0; i < 8; i++) {
                int c = g*8 + i;
                const float* xc = xn + c*HW;
                float4 v;
                v.x = c00[0]*__ldg(xc + i00[0]) + c01[0]*__ldg(xc + i01[0])
                    + c10[0]*__ldg(xc + i10[0]) + c11[0]*__ldg(xc + i11[0]);
                v.y = c00[1]*__ldg(xc + i00[1]) + c01[1]*__ldg(xc + i01[1])
                    + c10[1]*__ldg(xc + i10[1]) + c11[1]*__ldg(xc + i11[1]);
                v.z = c00[2]*__ldg(xc + i00[2]) + c01[2]*__ldg(xc + i01[2])
                    + c10[2]*__ldg(xc + i10[2]) + c11[2]*__ldg(xc + i11[2]);
                v.w = c00[3]*__ldg(xc + i00[3]) + c01[3]*__ldg(xc + i01[3])
                    + c10[3]*__ldg(xc + i10[3]) + c11[3]*__ldg(xc + i11[3]);
                *(float4*)(s_patch + c*64 + p0) = v;
            }
        }
        __syncthreads();
        #pragma unroll 4
        for (int c = 0; c < 64; c++) {
            float4 xq = *(const float4*)(s_patch + c*64 + p0);
            ulonglong2 wa = *(const ulonglong2*)(s_w + c*64 + g*8);
            ulonglong2 wb = *(const ulonglong2*)(s_w + c*64 + g*8 + 4);
            ull x0 = pack2(xq.x, xq.x);
            ull x1 = pack2(xq.y, xq.y);
            ull x2 = pack2(xq.z, xq.z);
            ull x3 = pack2(xq.w, xq.w);
            acc[0][0] = ffma2(x0, wa.x, acc[0][0]);
            acc[0][1] = ffma2(x0, wa.y, acc[0][1]);
            acc[0][2] = ffma2(x0, wb.x, acc[0][2]);
            acc[0][3] = ffma2(x0, wb.y, acc[0][3]);
            acc[1][0] = ffma2(x1, wa.x, acc[1][0]);
            acc[1][1] = ffma2(x1, wa.y, acc[1][1]);
            acc[1][2] = ffma2(x1, wb.x, acc[1][2]);
            acc[1][3] = ffma2(x1, wb.y, acc[1][3]);
            acc[2][0] = ffma2(x2, wa.x, acc[2][0]);
            acc[2][1] = ffma2(x2, wa.y, acc[2][1]);
            acc[2][2] = ffma2(x2, wb.x, acc[2][2]);
            acc[2][3] = ffma2(x2, wb.y, acc[2][3]);
            acc[3][0] = ffma2(x3, wa.x, acc[3][0]);
            acc[3][1] = ffma2(x3, wa.y, acc[3][1]);
            acc[3][2] = ffma2(x3, wb.x, acc[3][2]);
            acc[3][3] = ffma2(x3, wb.y, acc[3][3]);
        }
    }

    // ---------------- epilogue: 4-px STG.128 per co ----------------
    #pragma unroll
    for (int j = 0; j < 4; j++) {
        int co0 = g*8 + 2*j, co1 = co0 + 1;
        float b0 = __ldg(bias + co0);
        float b1 = __ldg(bias + co1);
        float2 v0 = unpack2(acc[0][j]);
        float2 v1 = unpack2(acc[1][j]);
        float2 v2 = unpack2(acc[2][j]);
        float2 v3 = unpack2(acc[3][j]);
        float4 o0 = make_float4(v0.x + b0, v1.x + b0, v2.x + b0, v3.x + b0);
        float4 o1 = make_float4(v0.y + b1, v1.y + b1, v2.y + b1, v3.y + b1);
        *(float4*)(out + ((n*COo + co0)*Hh + ph)*Ww + pw0) = o0;
        *(float4*)(out + ((n*COo + co1)*Hh + ph)*Ww + pw0) = o1;
    }
}

extern "C" void kernel_launch(void* const* d_in, const int* in_sizes, int n_in,
                              void* d_out, int out_size) {
    const float* x      = (const float*)d_in[0];
    const float* w_off  = (const float*)d_in[1];
    const float* b_off  = (const float*)d_in[2];
    const float* weight = (const float*)d_in[3];
    const float* bias   = (const float*)d_in[4];
    float* out = (float*)d_out;

    prep_weights<<<64, 256>>>(weight, w_off);
    dim3 grid(144, 8);
    fused_dcn<<<grid, 128>>>(x, b_off, bias, out);
}